// round 2
// baseline (speedup 1.0000x reference)
#include <cuda_runtime.h>
#include <cuda_bf16.h>

#define C_DIM 64
#define HC_DIM 256
#define N_MAX 50000
#define E_MAX 800000
#define T_MAX (N_MAX + E_MAX)

// Scratch (device globals; no allocation allowed)
__device__ float g_xl[(size_t)N_MAX * HC_DIM];
__device__ float g_xr[(size_t)N_MAX * HC_DIM];
__device__ int g_deg[N_MAX];
__device__ int g_cursor[N_MAX];
__device__ int g_off[N_MAX + 1];
__device__ int g_csr[T_MAX];

// ---------------------------------------------------------------------------
// GEMM: xl = x@W_l + b_l, xr = x@W_r + b_r   (blockIdx.y selects l/r)
// 16 rows x 256 cols per block, packed f32x2 FMA (2 rows per instruction).
// ---------------------------------------------------------------------------
__global__ void __launch_bounds__(256) gemm_kernel(
    const float* __restrict__ x,
    const float* __restrict__ Wl, const float* __restrict__ bl,
    const float* __restrict__ Wr, const float* __restrict__ br, int n) {
    const float* W = blockIdx.y ? Wr : Wl;
    const float* b = blockIdx.y ? br : bl;
    float* o = blockIdx.y ? g_xr : g_xl;

    __shared__ __align__(16) float xs[64][18];  // [k][row], 72B row stride (8B-divisible)
    int row0 = blockIdx.x * 16;
    int t = threadIdx.x;

    for (int i = t; i < 16 * 64; i += 256) {
        int r = i >> 6, c = i & 63;
        int row = row0 + r;
        xs[c][r] = (row < n) ? x[(size_t)row * C_DIM + c] : 0.f;
    }
    __syncthreads();

    unsigned long long acc2[8];
#pragma unroll
    for (int i = 0; i < 8; ++i) acc2[i] = 0ULL;

#pragma unroll
    for (int k = 0; k < 64; ++k) {
        float wv = W[k * HC_DIM + t];
        unsigned long long wv2;
        asm("mov.b64 %0, {%1, %1};" : "=l"(wv2) : "r"(__float_as_uint(wv)));
#pragma unroll
        for (int r2 = 0; r2 < 8; ++r2) {
            float2 xv = *(const float2*)&xs[k][r2 * 2];
            unsigned long long xv2;
            asm("mov.b64 %0, {%1, %2};"
                : "=l"(xv2)
                : "r"(__float_as_uint(xv.x)), "r"(__float_as_uint(xv.y)));
            asm("fma.rn.f32x2 %0, %1, %2, %0;"
                : "+l"(acc2[r2]) : "l"(xv2), "l"(wv2));
        }
    }

    float bb = b[t];
#pragma unroll
    for (int r2 = 0; r2 < 8; ++r2) {
        unsigned int lo, hi;
        asm("mov.b64 {%0, %1}, %2;" : "=r"(lo), "=r"(hi) : "l"(acc2[r2]));
        int row = row0 + 2 * r2;
        if (row < n)     o[(size_t)row * HC_DIM + t]       = __uint_as_float(lo) + bb;
        if (row + 1 < n) o[(size_t)(row + 1) * HC_DIM + t] = __uint_as_float(hi) + bb;
    }
}

// ---------------------------------------------------------------------------
// CSR build (edges are int32: src = edge[0:e], dst = edge[e:2e])
// ---------------------------------------------------------------------------
__global__ void init_kernel(int n) {
    int i = blockIdx.x * blockDim.x + threadIdx.x;
    if (i < n) {
        g_deg[i] = 1;  // self loop
        g_cursor[i] = 0;
    }
}

__global__ void hist_kernel(const int* __restrict__ edge, int e) {
    int i = blockIdx.x * blockDim.x + threadIdx.x;
    if (i < e) atomicAdd(&g_deg[edge[e + i]], 1);
}

// Single-block exclusive scan over g_deg -> g_off
__global__ void scan_kernel(int n) {
    __shared__ int part[1024];
    int t = threadIdx.x;
    int chunk = (n + 1023) >> 10;
    int lo = t * chunk;
    int hi = min(lo + chunk, n);
    int sum = 0;
    for (int i = lo; i < hi; ++i) sum += g_deg[i];
    part[t] = sum;
    __syncthreads();
    for (int off = 1; off < 1024; off <<= 1) {
        int v = (t >= off) ? part[t - off] : 0;
        __syncthreads();
        part[t] += v;
        __syncthreads();
    }
    int run = (t > 0) ? part[t - 1] : 0;
    for (int i = lo; i < hi; ++i) {
        g_off[i] = run;
        run += g_deg[i];
    }
    if (t == 1023) g_off[n] = part[1023];
}

__global__ void scatter_kernel(const int* __restrict__ edge, int e, int n) {
    int i = blockIdx.x * blockDim.x + threadIdx.x;
    if (i < e) {
        int d = edge[e + i];
        int pos = g_off[d] + atomicAdd(&g_cursor[d], 1);
        g_csr[pos] = edge[i];
    } else if (i < e + n) {
        int node = i - e;
        int pos = g_off[node] + atomicAdd(&g_cursor[node], 1);
        g_csr[pos] = node;
    }
}

// ---------------------------------------------------------------------------
// Fused per-node GATv2 aggregation with online softmax.
// One warp per node; lane owns 8 consecutive channels of the 256-wide (H*C)
// vector (all within one head: h = lane>>3).
// out[i,c] = mean_h( (sum_j e^{s-m} xl[j,h,c]) / (sum_j e^{s-m}) ) + bias[c]
// ---------------------------------------------------------------------------
__global__ void __launch_bounds__(256) agg_kernel(
    const float* __restrict__ att, const float* __restrict__ bias,
    float* __restrict__ out, int n) {
    int warp = (blockIdx.x * blockDim.x + threadIdx.x) >> 5;
    if (warp >= n) return;
    int lane = threadIdx.x & 31;
    int node = warp;
    int h = lane >> 3;
    int cbase = (lane & 7) * 8;

    float a[8], xrv[8];
    {
        const float4* ap = (const float4*)(att + h * C_DIM + cbase);
        float4 a0 = ap[0], a1 = ap[1];
        a[0] = a0.x; a[1] = a0.y; a[2] = a0.z; a[3] = a0.w;
        a[4] = a1.x; a[5] = a1.y; a[6] = a1.z; a[7] = a1.w;
        const float4* rp = (const float4*)(g_xr + (size_t)node * HC_DIM + lane * 8);
        float4 r0 = rp[0], r1 = rp[1];
        xrv[0] = r0.x; xrv[1] = r0.y; xrv[2] = r0.z; xrv[3] = r0.w;
        xrv[4] = r1.x; xrv[5] = r1.y; xrv[6] = r1.z; xrv[7] = r1.w;
    }

    float m = __int_as_float(0xff800000);  // -inf
    float s = 0.f;
    float acc[8];
#pragma unroll
    for (int k = 0; k < 8; ++k) acc[k] = 0.f;

    int p0 = g_off[node], p1 = g_off[node + 1];
    for (int p = p0; p < p1; ++p) {
        int j = g_csr[p];
        const float4* xp = (const float4*)(g_xl + (size_t)j * HC_DIM + lane * 8);
        float4 v0 = xp[0], v1 = xp[1];
        float xv[8] = {v0.x, v0.y, v0.z, v0.w, v1.x, v1.y, v1.z, v1.w};

        float sc = 0.f;
#pragma unroll
        for (int k = 0; k < 8; ++k) {
            float t = xv[k] + xrv[k];
            t = (t > 0.f) ? t : 0.2f * t;  // leaky_relu slope 0.2
            sc = fmaf(a[k], t, sc);
        }
        // reduce over the 8 lanes of this head
        sc += __shfl_xor_sync(0xffffffffu, sc, 1);
        sc += __shfl_xor_sync(0xffffffffu, sc, 2);
        sc += __shfl_xor_sync(0xffffffffu, sc, 4);

        float mn = fmaxf(m, sc);
        float fct = __expf(m - mn);   // exp(-inf)=0 on first edge
        float ex = __expf(sc - mn);
        s = fmaf(s, fct, ex);
#pragma unroll
        for (int k = 0; k < 8; ++k) acc[k] = fmaf(acc[k], fct, ex * xv[k]);
        m = mn;
    }

    float inv = 1.0f / s;
    float val[8];
#pragma unroll
    for (int k = 0; k < 8; ++k) val[k] = acc[k] * inv;
    // sum across heads (lanes l, l^8, l^16, l^24 hold same channel block)
#pragma unroll
    for (int k = 0; k < 8; ++k) val[k] += __shfl_xor_sync(0xffffffffu, val[k], 8);
#pragma unroll
    for (int k = 0; k < 8; ++k) val[k] += __shfl_xor_sync(0xffffffffu, val[k], 16);

    if (lane < 8) {
        const float4* bp = (const float4*)(bias + cbase);
        float4 b0 = bp[0], b1 = bp[1];
        float4 o0, o1;
        o0.x = val[0] * 0.25f + b0.x;
        o0.y = val[1] * 0.25f + b0.y;
        o0.z = val[2] * 0.25f + b0.z;
        o0.w = val[3] * 0.25f + b0.w;
        o1.x = val[4] * 0.25f + b1.x;
        o1.y = val[5] * 0.25f + b1.y;
        o1.z = val[6] * 0.25f + b1.z;
        o1.w = val[7] * 0.25f + b1.w;
        float4* op = (float4*)(out + (size_t)node * C_DIM + cbase);
        op[0] = o0;
        op[1] = o1;
    }
}

// ---------------------------------------------------------------------------
extern "C" void kernel_launch(void* const* d_in, const int* in_sizes, int n_in,
                              void* d_out, int out_size) {
    const float* x     = (const float*)d_in[0];
    const float* Wl    = (const float*)d_in[1];
    const float* bl    = (const float*)d_in[2];
    const float* Wr    = (const float*)d_in[3];
    const float* br    = (const float*)d_in[4];
    const float* att   = (const float*)d_in[5];
    const float* bias  = (const float*)d_in[6];
    const int*   edge  = (const int*)d_in[7];
    float* out = (float*)d_out;

    int n = in_sizes[0] / C_DIM;   // 50000
    int e = in_sizes[7] / 2;       // 800000

    dim3 ggrid((n + 15) / 16, 2);
    gemm_kernel<<<ggrid, 256>>>(x, Wl, bl, Wr, br, n);

    init_kernel<<<(n + 255) / 256, 256>>>(n);
    hist_kernel<<<(e + 255) / 256, 256>>>(edge, e);
    scan_kernel<<<1, 1024>>>(n);
    scatter_kernel<<<(e + n + 255) / 256, 256>>>(edge, e, n);

    agg_kernel<<<((size_t)n * 32 + 255) / 256, 256>>>(att, bias, out, n);
}

// round 3
// speedup vs baseline: 1.8346x; 1.8346x over previous
#include <cuda_runtime.h>
#include <cuda_bf16.h>

#define C_DIM 64
#define HC_DIM 256
#define N_MAX 50000
#define E_MAX 800000
#define T_MAX (N_MAX + E_MAX)
#define SCAN_B 1024

// Scratch (device globals; no allocation allowed)
__device__ float g_xl[(size_t)N_MAX * HC_DIM];
__device__ float g_xr[(size_t)N_MAX * HC_DIM];
__device__ int g_deg[N_MAX];
__device__ int g_cursor[N_MAX];
__device__ int g_off[N_MAX + 1];
__device__ int g_csr[T_MAX];
__device__ int g_bsum[64];
__device__ int g_bsumx[64];

// ---------------------------------------------------------------------------
// GEMM: xl = x@W_l + b_l, xr = x@W_r + b_r   (blockIdx.y selects l/r)
// ---------------------------------------------------------------------------
__global__ void __launch_bounds__(256) gemm_kernel(
    const float* __restrict__ x,
    const float* __restrict__ Wl, const float* __restrict__ bl,
    const float* __restrict__ Wr, const float* __restrict__ br, int n) {
    const float* W = blockIdx.y ? Wr : Wl;
    const float* b = blockIdx.y ? br : bl;
    float* o = blockIdx.y ? g_xr : g_xl;

    __shared__ __align__(16) float xs[64][18];
    int row0 = blockIdx.x * 16;
    int t = threadIdx.x;

    for (int i = t; i < 16 * 64; i += 256) {
        int r = i >> 6, c = i & 63;
        int row = row0 + r;
        xs[c][r] = (row < n) ? x[(size_t)row * C_DIM + c] : 0.f;
    }
    __syncthreads();

    unsigned long long acc2[8];
#pragma unroll
    for (int i = 0; i < 8; ++i) acc2[i] = 0ULL;

#pragma unroll
    for (int k = 0; k < 64; ++k) {
        float wv = W[k * HC_DIM + t];
        unsigned long long wv2;
        asm("mov.b64 %0, {%1, %1};" : "=l"(wv2) : "r"(__float_as_uint(wv)));
#pragma unroll
        for (int r2 = 0; r2 < 8; ++r2) {
            float2 xv = *(const float2*)&xs[k][r2 * 2];
            unsigned long long xv2;
            asm("mov.b64 %0, {%1, %2};"
                : "=l"(xv2)
                : "r"(__float_as_uint(xv.x)), "r"(__float_as_uint(xv.y)));
            asm("fma.rn.f32x2 %0, %1, %2, %0;"
                : "+l"(acc2[r2]) : "l"(xv2), "l"(wv2));
        }
    }

    float bb = b[t];
#pragma unroll
    for (int r2 = 0; r2 < 8; ++r2) {
        unsigned int lo, hi;
        asm("mov.b64 {%0, %1}, %2;" : "=r"(lo), "=r"(hi) : "l"(acc2[r2]));
        int row = row0 + 2 * r2;
        if (row < n)     o[(size_t)row * HC_DIM + t]       = __uint_as_float(lo) + bb;
        if (row + 1 < n) o[(size_t)(row + 1) * HC_DIM + t] = __uint_as_float(hi) + bb;
    }
}

// ---------------------------------------------------------------------------
// CSR build (edges are int32: src = edge[0:e], dst = edge[e:2e])
// ---------------------------------------------------------------------------
__global__ void init_kernel(int n) {
    int i = blockIdx.x * blockDim.x + threadIdx.x;
    if (i < n) {
        g_deg[i] = 1;  // self loop
        g_cursor[i] = 0;
    }
}

__global__ void hist_kernel(const int* __restrict__ edge, int e) {
    int i = blockIdx.x * blockDim.x + threadIdx.x;
    if (i < e) atomicAdd(&g_deg[edge[e + i]], 1);
}

__device__ __forceinline__ int warp_iscan(int v, int lane) {
#pragma unroll
    for (int o = 1; o < 32; o <<= 1) {
        int t = __shfl_up_sync(0xffffffffu, v, o);
        if (lane >= o) v += t;
    }
    return v;
}

// Phase 1: per-block exclusive scan of g_deg -> g_off (block-relative), block sums
__global__ void __launch_bounds__(SCAN_B) scan1_kernel(int n) {
    int t = threadIdx.x, lane = t & 31, w = t >> 5;
    int i = blockIdx.x * SCAN_B + t;
    int v = (i < n) ? g_deg[i] : 0;
    int inc = warp_iscan(v, lane);
    __shared__ int ws[32];
    if (lane == 31) ws[w] = inc;
    __syncthreads();
    if (w == 0) {
        int s = ws[lane];
        s = warp_iscan(s, lane);
        ws[lane] = s;
    }
    __syncthreads();
    int boff = w ? ws[w - 1] : 0;
    if (i < n) g_off[i] = inc - v + boff;
    if (t == SCAN_B - 1) g_bsum[blockIdx.x] = ws[31];
}

// Phase 2: exclusive scan of block sums (nb <= 64), plus total into g_off[n]
__global__ void scan2_kernel(int nb, int n) {
    __shared__ int s[64];
    int t = threadIdx.x;
    s[t] = (t < nb) ? g_bsum[t] : 0;
    __syncthreads();
    if (t == 0) {
        int run = 0;
        for (int i = 0; i < nb; ++i) {
            int v = s[i];
            g_bsumx[i] = run;
            run += v;
        }
        g_off[n] = run;
    }
}

// Phase 3: add block offsets
__global__ void __launch_bounds__(SCAN_B) scan3_kernel(int n) {
    int i = blockIdx.x * SCAN_B + threadIdx.x;
    if (i < n) g_off[i] += g_bsumx[blockIdx.x];
}

__global__ void scatter_kernel(const int* __restrict__ edge, int e, int n) {
    int i = blockIdx.x * blockDim.x + threadIdx.x;
    if (i < e) {
        int d = edge[e + i];
        int pos = g_off[d] + atomicAdd(&g_cursor[d], 1);
        g_csr[pos] = edge[i];
    } else if (i < e + n) {
        int node = i - e;
        int pos = g_off[node] + atomicAdd(&g_cursor[node], 1);
        g_csr[pos] = node;
    }
}

// ---------------------------------------------------------------------------
// Fused per-node GATv2 aggregation with online softmax + 1-deep prefetch.
// One warp per node; lane owns 8 consecutive channels (head h = lane>>3).
// ---------------------------------------------------------------------------
__global__ void __launch_bounds__(256) agg_kernel(
    const float* __restrict__ att, const float* __restrict__ bias,
    float* __restrict__ out, int n) {
    int warp = (blockIdx.x * blockDim.x + threadIdx.x) >> 5;
    if (warp >= n) return;
    int lane = threadIdx.x & 31;
    int node = warp;
    int h = lane >> 3;
    int cbase = (lane & 7) * 8;

    float a[8], xrv[8];
    {
        const float4* ap = (const float4*)(att + h * C_DIM + cbase);
        float4 a0 = ap[0], a1 = ap[1];
        a[0] = a0.x; a[1] = a0.y; a[2] = a0.z; a[3] = a0.w;
        a[4] = a1.x; a[5] = a1.y; a[6] = a1.z; a[7] = a1.w;
        const float4* rp = (const float4*)(g_xr + (size_t)node * HC_DIM + lane * 8);
        float4 r0 = rp[0], r1 = rp[1];
        xrv[0] = r0.x; xrv[1] = r0.y; xrv[2] = r0.z; xrv[3] = r0.w;
        xrv[4] = r1.x; xrv[5] = r1.y; xrv[6] = r1.z; xrv[7] = r1.w;
    }

    float m = __int_as_float(0xff800000);  // -inf
    float s = 0.f;
    float acc[8];
#pragma unroll
    for (int k = 0; k < 8; ++k) acc[k] = 0.f;

    int p0 = g_off[node], p1 = g_off[node + 1];
    // degree >= 1 always (self loop), so p0 < p1
    int j = g_csr[p0];
    const float4* xp = (const float4*)(g_xl + (size_t)j * HC_DIM + lane * 8);
    float4 v0 = xp[0], v1 = xp[1];

    for (int p = p0; p < p1; ++p) {
        float4 n0, n1;
        if (p + 1 < p1) {
            int jn = g_csr[p + 1];
            const float4* np = (const float4*)(g_xl + (size_t)jn * HC_DIM + lane * 8);
            n0 = np[0];
            n1 = np[1];
        }
        float xv[8] = {v0.x, v0.y, v0.z, v0.w, v1.x, v1.y, v1.z, v1.w};

        float sc = 0.f;
#pragma unroll
        for (int k = 0; k < 8; ++k) {
            float t = xv[k] + xrv[k];
            t = (t > 0.f) ? t : 0.2f * t;  // leaky_relu slope 0.2
            sc = fmaf(a[k], t, sc);
        }
        sc += __shfl_xor_sync(0xffffffffu, sc, 1);
        sc += __shfl_xor_sync(0xffffffffu, sc, 2);
        sc += __shfl_xor_sync(0xffffffffu, sc, 4);

        float mn = fmaxf(m, sc);
        float fct = __expf(m - mn);
        float ex = __expf(sc - mn);
        s = fmaf(s, fct, ex);
#pragma unroll
        for (int k = 0; k < 8; ++k) acc[k] = fmaf(acc[k], fct, ex * xv[k]);
        m = mn;

        v0 = n0;
        v1 = n1;
    }

    float inv = 1.0f / s;
    float val[8];
#pragma unroll
    for (int k = 0; k < 8; ++k) val[k] = acc[k] * inv;
#pragma unroll
    for (int k = 0; k < 8; ++k) val[k] += __shfl_xor_sync(0xffffffffu, val[k], 8);
#pragma unroll
    for (int k = 0; k < 8; ++k) val[k] += __shfl_xor_sync(0xffffffffu, val[k], 16);

    if (lane < 8) {
        const float4* bp = (const float4*)(bias + cbase);
        float4 b0 = bp[0], b1 = bp[1];
        float4 o0, o1;
        o0.x = val[0] * 0.25f + b0.x;
        o0.y = val[1] * 0.25f + b0.y;
        o0.z = val[2] * 0.25f + b0.z;
        o0.w = val[3] * 0.25f + b0.w;
        o1.x = val[4] * 0.25f + b1.x;
        o1.y = val[5] * 0.25f + b1.y;
        o1.z = val[6] * 0.25f + b1.z;
        o1.w = val[7] * 0.25f + b1.w;
        float4* op = (float4*)(out + (size_t)node * C_DIM + cbase);
        op[0] = o0;
        op[1] = o1;
    }
}

// ---------------------------------------------------------------------------
extern "C" void kernel_launch(void* const* d_in, const int* in_sizes, int n_in,
                              void* d_out, int out_size) {
    const float* x     = (const float*)d_in[0];
    const float* Wl    = (const float*)d_in[1];
    const float* bl    = (const float*)d_in[2];
    const float* Wr    = (const float*)d_in[3];
    const float* br    = (const float*)d_in[4];
    const float* att   = (const float*)d_in[5];
    const float* bias  = (const float*)d_in[6];
    const int*   edge  = (const int*)d_in[7];
    float* out = (float*)d_out;

    int n = in_sizes[0] / C_DIM;   // 50000
    int e = in_sizes[7] / 2;       // 800000
    int nb = (n + SCAN_B - 1) / SCAN_B;

    dim3 ggrid((n + 15) / 16, 2);
    gemm_kernel<<<ggrid, 256>>>(x, Wl, bl, Wr, br, n);

    init_kernel<<<(n + 255) / 256, 256>>>(n);
    hist_kernel<<<(e + 255) / 256, 256>>>(edge, e);
    scan1_kernel<<<nb, SCAN_B>>>(n);
    scan2_kernel<<<1, 64>>>(nb, n);
    scan3_kernel<<<nb, SCAN_B>>>(n);
    scatter_kernel<<<(e + n + 255) / 256, 256>>>(edge, e, n);

    agg_kernel<<<((size_t)n * 32 + 255) / 256, 256>>>(att, bias, out, n);
}